// round 17
// baseline (speedup 1.0000x reference)
#include <cuda_runtime.h>
#include <cuda_bf16.h>

// Locked best configuration (50.944 us) with ONE remaining untested
// single-variable probe: output stores use st.global.wt (write-through,
// __stwt). Unlike __stcs (evict-first, still L2 write-allocating), the
// write-through policy removes the output stream from L2 dirty-line
// management entirely; stores are full 128B coalesced sectors that are
// never re-read, so L2 allocation for them is pure overhead if nonzero.
// Read side keeps plain __ldg (best measured).
//
// One-pass fused preprocessing, [16,1280,960,3] f32 -> [16,3,640,640] f32:
// cast+rescale(1/255) -> bilinear resize (half-pixel centers, no antialias)
// -> normalize (mean/std) -> NHWC->NCHW.
//
// Math: vertical scale exactly 2.0 -> output row y = average of input rows
// 2y,2y+1 (done during staging). Horizontal 1.5 -> px group {4t..4t+3}
// reads input cols {6t..6t+5}, fracs {.25,.75,.25,.75}; no clamping.
// rescale+normalize fold to one FMA per channel; 3 divides per block.
//
// Schedule: one block per (output row, batch), 10240 x 240 threads;
// float4-coalesced staging of both rows averaged into one 2880-float smem
// row (11.5 KB); single __syncthreads; 160 threads x 4 px compute with one
// float4 store per channel plane; 32 regs -> 60 warps/SM.

#define IN_H    1280
#define IN_W    960
#define OUT_HW  640
#define ROW_F   (IN_W * 3)     // 2880 floats per input row
#define ROW_F4  (ROW_F / 4)    // 720 float4
#define NT      240            // 720 float4 / 240 threads = 3 staging iters
#define PLANE   (OUT_HW * OUT_HW)

__global__ __launch_bounds__(NT) void preproc_final_kernel(
    const float* __restrict__ img,   // [16, 1280, 960, 3]
    const float* __restrict__ mean,  // [3]
    const float* __restrict__ stdv,  // [3]
    float* __restrict__ out)         // [16, 3, 640, 640]
{
    __shared__ float s_row[ROW_F];      // vertically averaged input row
    __shared__ float s_scale[3];
    __shared__ float s_bias[3];

    const int t = threadIdx.x;
    if (t < 3) {
        const float inv = 1.0f / stdv[t];
        s_scale[t] = (1.0f / 255.0f) * inv;
        s_bias[t]  = -mean[t] * inv;
    }

    const int y = blockIdx.x;   // 0..639
    const int b = blockIdx.y;   // 0..15

    // stage: rows 2y, 2y+1 -> averaged row in smem (float4 coalesced)
    const float4* __restrict__ r0 =
        (const float4*)(img + (size_t)(b * IN_H + 2 * y) * ROW_F);
    const float4* __restrict__ r1 = r0 + ROW_F4;
    float4* s4 = (float4*)s_row;
#pragma unroll
    for (int j = 0; j < 3; ++j) {
        const int idx = t + j * NT;
        float4 a = __ldg(&r0[idx]);
        float4 c = __ldg(&r1[idx]);
        float4 m;
        m.x = 0.5f * (a.x + c.x);
        m.y = 0.5f * (a.y + c.y);
        m.z = 0.5f * (a.z + c.z);
        m.w = 0.5f * (a.w + c.w);
        s4[idx] = m;
    }
    __syncthreads();

    // compute: 4 output px per thread, threads 0..159
    if (t < 160) {
        float v[18];
        const float2* sp = (const float2*)&s_row[18 * t];  // 72B stride, 8B ok
#pragma unroll
        for (int j = 0; j < 9; ++j) {
            float2 p = sp[j];
            v[2 * j]     = p.x;
            v[2 * j + 1] = p.y;
        }

        const int ob = b * 3 * PLANE + y * OUT_HW + 4 * t;
#pragma unroll
        for (int c = 0; c < 3; ++c) {
            const float a0 = v[c],      a1 = v[3 + c],  a2 = v[6 + c];
            const float a3 = v[9 + c],  a4 = v[12 + c], a5 = v[15 + c];
            float4 o;
            o.x = fmaf(a1 - a0, 0.25f, a0);   // x = 4t   (fx = .25)
            o.y = fmaf(a2 - a1, 0.75f, a1);   // x = 4t+1 (fx = .75)
            o.z = fmaf(a4 - a3, 0.25f, a3);   // x = 4t+2
            o.w = fmaf(a5 - a4, 0.75f, a4);   // x = 4t+3
            const float sc = s_scale[c], bi = s_bias[c];
            o.x = fmaf(o.x, sc, bi);
            o.y = fmaf(o.y, sc, bi);
            o.z = fmaf(o.z, sc, bi);
            o.w = fmaf(o.w, sc, bi);
            __stwt((float4*)&out[ob + c * PLANE], o);   // write-through
        }
    }
}

extern "C" void kernel_launch(void* const* d_in, const int* in_sizes, int n_in,
                              void* d_out, int out_size) {
    const float* img  = (const float*)d_in[0];
    const float* mean = (const float*)d_in[1];
    const float* stdv = (const float*)d_in[2];
    float* out = (float*)d_out;

    dim3 block(NT, 1, 1);
    dim3 grid(OUT_HW, 16, 1);   // (640 rows, 16 batches)
    preproc_final_kernel<<<grid, block>>>(img, mean, stdv, out);
}